// round 1
// baseline (speedup 1.0000x reference)
#include <cuda_runtime.h>

#define NCOLS     16384
#define KSEL      655u
#define NTHREADS  512
#define NIT       8              // NCOLS / (NTHREADS*4)

// shared layout (uint32 words)
#define OFF_KEYS  0
#define OFF_HIST  (OFF_KEYS + NCOLS)     // 2048 bins
#define OFF_GSUM  (OFF_HIST + 2048)      // 64 group sums
#define OFF_RED   (OFF_GSUM + 64)        // 16 warps * 8 counters
#define OFF_BC    (OFF_RED + 128)        // broadcast slots
#define SMEM_UINTS (OFF_BC + 8)
#define SMEM_BYTES (SMEM_UINTS * 4)

__device__ float g_boost[NCOLS];

__global__ void boost_kernel(const float* __restrict__ duty) {
    int i = blockIdx.x * blockDim.x + threadIdx.x;
    if (i < NCOLS) {
        const float target = 655.0f / 16384.0f;   // exact in f32
        float d = target - duty[i];               // same f32 op as reference
        g_boost[i] = (float)exp((double)d);       // correctly-rounded f32 exp
    }
}

// monotonic float->uint transform: order(key) == order(float)
__device__ __forceinline__ unsigned fkey(float f) {
    unsigned u = __float_as_uint(f);
    return (u & 0x80000000u) ? ~u : (u | 0x80000000u);
}

// Find, scanning bins from high to low, the first bin where cumulative count
// reaches `need`. Outputs: bc[0]=bin, bc[1]=remaining needed within bin, bc[5]=bin count.
__device__ __forceinline__ void scan_select(unsigned* hist, int nbins, unsigned need,
                                            unsigned* gsum, unsigned* bc) {
    int tid = threadIdx.x;
    int gsz = nbins >> 6;
    if (tid < 64) {
        unsigned s = 0;
        for (int i = 0; i < gsz; i++) s += hist[tid * gsz + i];
        gsum[tid] = s;
    }
    __syncthreads();
    if (tid == 0) {
        unsigned cum = 0;
        int g = 63;
        for (; g > 0; g--) {
            if (cum + gsum[g] >= need) break;
            cum += gsum[g];
        }
        int b = g * gsz + gsz - 1;
        for (; b > g * gsz; b--) {
            if (cum + hist[b] >= need) break;
            cum += hist[b];
        }
        bc[0] = (unsigned)b;
        bc[1] = need - cum;
        bc[5] = hist[b];
    }
    __syncthreads();
}

__global__ void __launch_bounds__(NTHREADS, 3)
kwinners_kernel(const float* __restrict__ x, float* __restrict__ out) {
    extern __shared__ unsigned sh[];
    unsigned* keys = sh + OFF_KEYS;
    unsigned* hist = sh + OFF_HIST;
    unsigned* gsum = sh + OFF_GSUM;
    unsigned* red  = sh + OFF_RED;
    unsigned* bc   = sh + OFF_BC;

    const int tid = threadIdx.x;
    const int row = blockIdx.x;
    const float4* xin  = reinterpret_cast<const float4*>(x + (size_t)row * NCOLS);
    const float4* bfv  = reinterpret_cast<const float4*>(g_boost);
    uint4*        keys4 = reinterpret_cast<uint4*>(keys);

    // coarse candidate thresholds (descending), aligned to pass-1 bins (low 21 bits clear)
    unsigned Bk[8];
    {
        const float bvals[7] = {3.0f, 2.0f, 1.5f, 1.25f, 1.0f, 0.75f, 0.5f};
        #pragma unroll
        for (int i = 0; i < 7; i++)
            Bk[i] = (__float_as_uint(bvals[i]) | 0x80000000u) & ~0x1FFFFFu;
        Bk[7] = 0u;   // catch-all: always >= K candidates
    }

    // clear histogram (covered by later syncs before first atomic)
    #pragma unroll
    for (int i = 0; i < 4; i++) hist[tid + i * NTHREADS] = 0;

    unsigned cnt[8] = {0,0,0,0,0,0,0,0};

    // load + boost + key transform + stash in SMEM + coarse counting (no atomics)
    #pragma unroll
    for (int it = 0; it < NIT; it++) {
        int i4 = it * NTHREADS + tid;
        float4 xv = __ldg(&xin[i4]);
        float4 bv = __ldg(&bfv[i4]);
        uint4 k;
        k.x = fkey(xv.x * bv.x);
        k.y = fkey(xv.y * bv.y);
        k.z = fkey(xv.z * bv.z);
        k.w = fkey(xv.w * bv.w);
        keys4[i4] = k;
        #pragma unroll
        for (int b = 0; b < 8; b++)
            cnt[b] += (unsigned)(k.x >= Bk[b]) + (unsigned)(k.y >= Bk[b])
                    + (unsigned)(k.z >= Bk[b]) + (unsigned)(k.w >= Bk[b]);
    }

    // reduce coarse counters across block
    #pragma unroll
    for (int b = 0; b < 8; b++) {
        unsigned v = __reduce_add_sync(0xFFFFFFFFu, cnt[b]);
        if ((tid & 31) == 0) red[(tid >> 5) * 8 + b] = v;
    }
    __syncthreads();
    if (tid < 8) {
        unsigned s = 0;
        #pragma unroll
        for (int w = 0; w < 16; w++) s += red[w * 8 + tid];
        red[tid] = s;   // totals
    }
    __syncthreads();
    if (tid == 0) {
        #pragma unroll
        for (int i = 0; i < 8; i++) {
            if (red[i] >= KSEL) { bc[2] = Bk[i]; break; }
        }
    }
    __syncthreads();
    const unsigned Bsel = bc[2];

    // ---- pass 1: top-11-bit histogram over candidates only ----
    #pragma unroll
    for (int it = 0; it < NIT; it++) {
        uint4 k = keys4[it * NTHREADS + tid];
        if (k.x >= Bsel) atomicAdd(&hist[k.x >> 21], 1u);
        if (k.y >= Bsel) atomicAdd(&hist[k.y >> 21], 1u);
        if (k.z >= Bsel) atomicAdd(&hist[k.z >> 21], 1u);
        if (k.w >= Bsel) atomicAdd(&hist[k.w >> 21], 1u);
    }
    __syncthreads();
    scan_select(hist, 2048, KSEL, gsum, bc);
    const unsigned b1   = bc[0];
    const unsigned rem1 = bc[1];

    #pragma unroll
    for (int i = 0; i < 4; i++) hist[tid + i * NTHREADS] = 0;
    __syncthreads();

    // ---- pass 2: middle 11 bits within bin b1 ----
    #pragma unroll
    for (int it = 0; it < NIT; it++) {
        uint4 k = keys4[it * NTHREADS + tid];
        if ((k.x >> 21) == b1) atomicAdd(&hist[(k.x >> 10) & 2047u], 1u);
        if ((k.y >> 21) == b1) atomicAdd(&hist[(k.y >> 10) & 2047u], 1u);
        if ((k.z >> 21) == b1) atomicAdd(&hist[(k.z >> 10) & 2047u], 1u);
        if ((k.w >> 21) == b1) atomicAdd(&hist[(k.w >> 10) & 2047u], 1u);
    }
    __syncthreads();
    scan_select(hist, 2048, rem1, gsum, bc);
    const unsigned b2     = bc[0];
    const unsigned rem2   = bc[1];
    const unsigned pref21 = (b1 << 11) | b2;   // == key >> 10

    #pragma unroll
    for (int i = 0; i < 2; i++) hist[tid + i * NTHREADS] = 0;
    __syncthreads();

    // ---- pass 3: low 10 bits within prefix ----
    #pragma unroll
    for (int it = 0; it < NIT; it++) {
        uint4 k = keys4[it * NTHREADS + tid];
        if ((k.x >> 10) == pref21) atomicAdd(&hist[k.x & 1023u], 1u);
        if ((k.y >> 10) == pref21) atomicAdd(&hist[k.y & 1023u], 1u);
        if ((k.z >> 10) == pref21) atomicAdd(&hist[k.z & 1023u], 1u);
        if ((k.w >> 10) == pref21) atomicAdd(&hist[k.w & 1023u], 1u);
    }
    __syncthreads();
    scan_select(hist, 1024, rem2, gsum, bc);
    const unsigned T    = (pref21 << 10) | bc[0];  // exact K-th largest key
    const unsigned rem3 = bc[1];                   // how many ==T to select
    const unsigned Ecnt = bc[5];                   // how many ==T exist

    if (tid == 0) {
        if (rem3 == Ecnt) {
            bc[3] = NCOLS - 1;                     // select all equals (common case)
        } else {
            // stable tie-break: first rem3 equals in index order (matches top_k)
            unsigned c = 0, idx = NCOLS - 1;
            for (int i = 0; i < NCOLS; i++) {
                if (keys[i] == T) { if (++c == rem3) { idx = (unsigned)i; break; } }
            }
            bc[3] = idx;
        }
    }
    __syncthreads();
    const unsigned Ithr = bc[3];

    // ---- emit binary mask ----
    float4* out4 = reinterpret_cast<float4*>(out + (size_t)row * NCOLS);
    #pragma unroll
    for (int it = 0; it < NIT; it++) {
        int i4 = it * NTHREADS + tid;
        uint4 k = keys4[i4];
        unsigned base = (unsigned)i4 * 4u;
        float4 o;
        o.x = (k.x > T || (k.x == T && base + 0u <= Ithr)) ? 1.0f : 0.0f;
        o.y = (k.y > T || (k.y == T && base + 1u <= Ithr)) ? 1.0f : 0.0f;
        o.z = (k.z > T || (k.z == T && base + 2u <= Ithr)) ? 1.0f : 0.0f;
        o.w = (k.w > T || (k.w == T && base + 3u <= Ithr)) ? 1.0f : 0.0f;
        out4[i4] = o;
    }
}

extern "C" void kernel_launch(void* const* d_in, const int* in_sizes, int n_in,
                              void* d_out, int out_size) {
    const float* x    = (const float*)d_in[0];
    const float* duty = (const float*)d_in[1];
    float* out        = (float*)d_out;
    int rows = in_sizes[0] / NCOLS;

    cudaFuncSetAttribute(kwinners_kernel,
                         cudaFuncAttributeMaxDynamicSharedMemorySize, SMEM_BYTES);

    boost_kernel<<<(NCOLS + 255) / 256, 256>>>(duty);
    kwinners_kernel<<<rows, NTHREADS, SMEM_BYTES>>>(x, out);
}

// round 2
// speedup vs baseline: 1.1537x; 1.1537x over previous
#include <cuda_runtime.h>

#define NCOLS     16384
#define KSEL      655u
#define NTHREADS  512
#define NIT       8              // NCOLS / (NTHREADS*4)
#define CAP       4096u          // candidate buffer capacity

// shared layout (uint32 words)
#define OFF_CAND  0                          // CAP uint2 = 2*CAP words
#define OFF_HIST  (OFF_CAND + 2*CAP)         // 2048 bins
#define OFF_GSUM  (OFF_HIST + 2048)          // 64
#define OFF_BC    (OFF_GSUM + 64)            // 8 broadcast slots
#define OFF_CNT   (OFF_BC + 8)               // 1 counter
#define SMEM_UINTS (OFF_CNT + 1)
#define SMEM_BYTES (SMEM_UINTS * 4)

__device__ float g_boost[NCOLS];

__global__ void boost_kernel(const float* __restrict__ duty) {
    int i = blockIdx.x * blockDim.x + threadIdx.x;
    if (i < NCOLS) {
        const float target = 655.0f / 16384.0f;   // exact in f32
        float d = target - duty[i];               // same f32 op as reference
        g_boost[i] = (float)exp((double)d);       // correctly-rounded f32 exp
    }
}

// monotonic float->uint transform: order(key) == order(float)
__device__ __forceinline__ unsigned fkey(float f) {
    unsigned u = __float_as_uint(f);
    return u ^ (((unsigned)((int)u >> 31)) | 0x80000000u);
}

__device__ __forceinline__ uint4 keys4_at(const float4* __restrict__ xin,
                                          const float4* __restrict__ bfv, int i4) {
    float4 xv = __ldg(&xin[i4]);
    float4 bv = __ldg(&bfv[i4]);
    uint4 k;
    k.x = fkey(xv.x * bv.x);
    k.y = fkey(xv.y * bv.y);
    k.z = fkey(xv.z * bv.z);
    k.w = fkey(xv.w * bv.w);
    return k;
}

// Parallel "find bin where cumulative count from the top reaches `need`".
// Outputs: bc[0]=bin, bc[1]=remaining needed within bin, bc[5]=bin count.
__device__ __forceinline__ void scan_sel(unsigned* hist, int nbins, unsigned need,
                                         unsigned* gsum, unsigned* bc) {
    const int tid = threadIdx.x;
    const int gsz = nbins >> 6;
    if (tid == 0) { bc[6] = 0u; bc[7] = 0u; }
    if (tid < 64) {
        unsigned s = 0;
        for (int i = 0; i < gsz; i++) s += hist[tid * gsz + i];
        gsum[tid] = s;
    }
    __syncthreads();
    unsigned suf = 0;
    if (tid < 64) {
        for (int j = tid; j < 64; j++) suf += gsum[j];
    }
    __syncthreads();
    if (tid < 64) {
        gsum[tid] = suf;                       // group suffix sums
        if (suf >= need) atomicMax(&bc[6], 0x10000u | (unsigned)tid);
    }
    __syncthreads();
    const unsigned g = bc[6] & 0xFFFFu;        // largest group with suffix >= need
    const unsigned cumAbove = (g == 63u) ? 0u : gsum[g + 1];
    __syncthreads();
    const unsigned need2 = need - cumAbove;
    if (tid < gsz) {
        unsigned s2 = 0;
        for (int j = (int)g * gsz + tid; j < ((int)g + 1) * gsz; j++) s2 += hist[j];
        gsum[tid] = s2;                        // within-group bin suffix sums
        if (s2 >= need2) atomicMax(&bc[7], 0x10000u | (unsigned)tid);
    }
    __syncthreads();
    if (tid == 0) {
        unsigned bl = bc[7] & 0xFFFFu;
        unsigned b = g * (unsigned)gsz + bl;
        unsigned cum2 = (bl == (unsigned)(gsz - 1)) ? 0u : gsum[bl + 1];
        bc[0] = b;
        bc[1] = need2 - cum2;
        bc[5] = hist[b];
    }
    __syncthreads();
}

__global__ void __launch_bounds__(NTHREADS, 4)
kwinners_kernel(const float* __restrict__ x, float* __restrict__ out) {
    extern __shared__ unsigned sh[];
    uint2*    cand = reinterpret_cast<uint2*>(sh + OFF_CAND);
    unsigned* hist = sh + OFF_HIST;
    unsigned* gsum = sh + OFF_GSUM;
    unsigned* bc   = sh + OFF_BC;
    unsigned* scnt = sh + OFF_CNT;

    const int tid  = threadIdx.x;
    const int lane = tid & 31;
    const int row  = blockIdx.x;
    const float4* xin  = reinterpret_cast<const float4*>(x + (size_t)row * NCOLS);
    const float4* bfv  = reinterpret_cast<const float4*>(g_boost);
    float*  outrow = out + (size_t)row * NCOLS;
    float4* out4   = reinterpret_cast<float4*>(outrow);

    const unsigned T0 = fkey(0.8f);   // static candidate threshold

    if (tid == 0) *scnt = 0;
    #pragma unroll
    for (int i = 0; i < 4; i++) hist[tid + i * NTHREADS] = 0;
    __syncthreads();

    const float4 z4 = make_float4(0.f, 0.f, 0.f, 0.f);

    // ---- single full-N pass: load, key, zero-out, compact candidates ----
    #pragma unroll
    for (int it = 0; it < NIT; it++) {
        int i4 = it * NTHREADS + tid;
        uint4 k = keys4_at(xin, bfv, i4);
        out4[i4] = z4;                         // stream zeros now
        unsigned p0 = (k.x >= T0), p1 = (k.y >= T0);
        unsigned p2 = (k.z >= T0), p3 = (k.w >= T0);
        unsigned nc = p0 + p1 + p2 + p3;
        // warp-wide inclusive prefix of nc
        unsigned pre = nc;
        #pragma unroll
        for (int d = 1; d < 32; d <<= 1) {
            unsigned v = __shfl_up_sync(0xFFFFFFFFu, pre, d);
            if (lane >= d) pre += v;
        }
        unsigned tot = __shfl_sync(0xFFFFFFFFu, pre, 31);
        unsigned base = 0;
        if (lane == 31 && tot) base = atomicAdd(scnt, tot);
        base = __shfl_sync(0xFFFFFFFFu, base, 31);
        unsigned pos = base + pre - nc;
        unsigned bi = (unsigned)i4 * 4u;
        if (p0) { if (pos < CAP) cand[pos] = make_uint2(k.x, bi + 0u); pos++; }
        if (p1) { if (pos < CAP) cand[pos] = make_uint2(k.y, bi + 1u); pos++; }
        if (p2) { if (pos < CAP) cand[pos] = make_uint2(k.z, bi + 2u); pos++; }
        if (p3) { if (pos < CAP) cand[pos] = make_uint2(k.w, bi + 3u); pos++; }
    }
    __syncthreads();
    const unsigned total = *scnt;

    if (total >= KSEL && total <= CAP) {
        // ================= FAST PATH: radix select on candidates =================
        const unsigned C = total;
        for (unsigned i = tid; i < C; i += NTHREADS)
            atomicAdd(&hist[cand[i].x >> 21], 1u);
        __syncthreads();
        scan_sel(hist, 2048, KSEL, gsum, bc);
        const unsigned b1 = bc[0], rem1 = bc[1];

        #pragma unroll
        for (int i = 0; i < 4; i++) hist[tid + i * NTHREADS] = 0;
        __syncthreads();
        for (unsigned i = tid; i < C; i += NTHREADS) {
            unsigned k = cand[i].x;
            if ((k >> 21) == b1) atomicAdd(&hist[(k >> 10) & 2047u], 1u);
        }
        __syncthreads();
        scan_sel(hist, 2048, rem1, gsum, bc);
        const unsigned b2 = bc[0], rem2 = bc[1];
        const unsigned pref21 = (b1 << 11) | b2;

        #pragma unroll
        for (int i = 0; i < 2; i++) hist[tid + i * NTHREADS] = 0;
        __syncthreads();
        for (unsigned i = tid; i < C; i += NTHREADS) {
            unsigned k = cand[i].x;
            if ((k >> 10) == pref21) atomicAdd(&hist[k & 1023u], 1u);
        }
        __syncthreads();
        scan_sel(hist, 1024, rem2, gsum, bc);
        const unsigned T    = (pref21 << 10) | bc[0];
        const unsigned rem3 = bc[1];
        const unsigned Ecnt = bc[5];

        if (tid == 0) {
            if (rem3 == Ecnt) {
                bc[3] = 0xFFFFFFFFu;             // select all equals
            } else {
                // rare: pick rem3 smallest indices among equals (stable top_k)
                unsigned cnt = 0;
                for (unsigned i = 0; i < C && cnt < 2048u; i++)
                    if (cand[i].x == T) hist[cnt++] = cand[i].y;
                unsigned Ith = 0;
                for (unsigned r = 0; r < rem3; r++) {
                    unsigned best = 0xFFFFFFFFu, bj = 0;
                    for (unsigned j = 0; j < cnt; j++)
                        if (hist[j] < best) { best = hist[j]; bj = j; }
                    hist[bj] = 0xFFFFFFFFu;
                    Ith = best;
                }
                bc[3] = Ith;
            }
        }
        __syncthreads();
        const unsigned Ithr = bc[3];

        // scatter winners over the zeroed row
        for (unsigned i = tid; i < C; i += NTHREADS) {
            uint2 c = cand[i];
            if (c.x > T || (c.x == T && c.y <= Ithr)) outrow[c.y] = 1.0f;
        }
    } else {
        // ================= FALLBACK: exact full radix, recompute keys =================
        #pragma unroll
        for (int it = 0; it < NIT; it++) {
            uint4 k = keys4_at(xin, bfv, it * NTHREADS + tid);
            atomicAdd(&hist[k.x >> 21], 1u);
            atomicAdd(&hist[k.y >> 21], 1u);
            atomicAdd(&hist[k.z >> 21], 1u);
            atomicAdd(&hist[k.w >> 21], 1u);
        }
        __syncthreads();
        scan_sel(hist, 2048, KSEL, gsum, bc);
        const unsigned b1 = bc[0], rem1 = bc[1];
        #pragma unroll
        for (int i = 0; i < 4; i++) hist[tid + i * NTHREADS] = 0;
        __syncthreads();
        #pragma unroll
        for (int it = 0; it < NIT; it++) {
            uint4 k = keys4_at(xin, bfv, it * NTHREADS + tid);
            if ((k.x >> 21) == b1) atomicAdd(&hist[(k.x >> 10) & 2047u], 1u);
            if ((k.y >> 21) == b1) atomicAdd(&hist[(k.y >> 10) & 2047u], 1u);
            if ((k.z >> 21) == b1) atomicAdd(&hist[(k.z >> 10) & 2047u], 1u);
            if ((k.w >> 21) == b1) atomicAdd(&hist[(k.w >> 10) & 2047u], 1u);
        }
        __syncthreads();
        scan_sel(hist, 2048, rem1, gsum, bc);
        const unsigned b2 = bc[0], rem2 = bc[1];
        const unsigned pref21 = (b1 << 11) | b2;
        #pragma unroll
        for (int i = 0; i < 2; i++) hist[tid + i * NTHREADS] = 0;
        __syncthreads();
        #pragma unroll
        for (int it = 0; it < NIT; it++) {
            uint4 k = keys4_at(xin, bfv, it * NTHREADS + tid);
            if ((k.x >> 10) == pref21) atomicAdd(&hist[k.x & 1023u], 1u);
            if ((k.y >> 10) == pref21) atomicAdd(&hist[k.y & 1023u], 1u);
            if ((k.z >> 10) == pref21) atomicAdd(&hist[k.z & 1023u], 1u);
            if ((k.w >> 10) == pref21) atomicAdd(&hist[k.w & 1023u], 1u);
        }
        __syncthreads();
        scan_sel(hist, 1024, rem2, gsum, bc);
        const unsigned T    = (pref21 << 10) | bc[0];
        const unsigned rem3 = bc[1];
        const unsigned Ecnt = bc[5];

        if (rem3 != Ecnt) {
            if (tid == 0) *scnt = 0;
            __syncthreads();
            #pragma unroll
            for (int it = 0; it < NIT; it++) {
                int i4 = it * NTHREADS + tid;
                uint4 k = keys4_at(xin, bfv, i4);
                unsigned bi = (unsigned)i4 * 4u;
                if (k.x == T) { unsigned p = atomicAdd(scnt, 1u); if (p < CAP) cand[p].y = bi + 0u; }
                if (k.y == T) { unsigned p = atomicAdd(scnt, 1u); if (p < CAP) cand[p].y = bi + 1u; }
                if (k.z == T) { unsigned p = atomicAdd(scnt, 1u); if (p < CAP) cand[p].y = bi + 2u; }
                if (k.w == T) { unsigned p = atomicAdd(scnt, 1u); if (p < CAP) cand[p].y = bi + 3u; }
            }
            __syncthreads();
            if (tid == 0) {
                unsigned cnt = *scnt; if (cnt > CAP) cnt = CAP;
                unsigned Ith = 0;
                for (unsigned r = 0; r < rem3; r++) {
                    unsigned best = 0xFFFFFFFFu, bj = 0;
                    for (unsigned j = 0; j < cnt; j++)
                        if (cand[j].y < best) { best = cand[j].y; bj = j; }
                    cand[bj].y = 0xFFFFFFFFu;
                    Ith = best;
                }
                bc[3] = Ith;
            }
        } else if (tid == 0) {
            bc[3] = 0xFFFFFFFFu;
        }
        __syncthreads();
        const unsigned Ithr = bc[3];

        #pragma unroll
        for (int it = 0; it < NIT; it++) {
            int i4 = it * NTHREADS + tid;
            uint4 k = keys4_at(xin, bfv, i4);
            unsigned bi = (unsigned)i4 * 4u;
            float4 o;
            o.x = (k.x > T || (k.x == T && bi + 0u <= Ithr)) ? 1.0f : 0.0f;
            o.y = (k.y > T || (k.y == T && bi + 1u <= Ithr)) ? 1.0f : 0.0f;
            o.z = (k.z > T || (k.z == T && bi + 2u <= Ithr)) ? 1.0f : 0.0f;
            o.w = (k.w > T || (k.w == T && bi + 3u <= Ithr)) ? 1.0f : 0.0f;
            out4[i4] = o;
        }
    }
}

extern "C" void kernel_launch(void* const* d_in, const int* in_sizes, int n_in,
                              void* d_out, int out_size) {
    const float* x    = (const float*)d_in[0];
    const float* duty = (const float*)d_in[1];
    float* out        = (float*)d_out;
    int rows = in_sizes[0] / NCOLS;

    cudaFuncSetAttribute(kwinners_kernel,
                         cudaFuncAttributeMaxDynamicSharedMemorySize, SMEM_BYTES);

    boost_kernel<<<(NCOLS + 255) / 256, 256>>>(duty);
    kwinners_kernel<<<rows, NTHREADS, SMEM_BYTES>>>(x, out);
}

// round 3
// speedup vs baseline: 1.1696x; 1.0138x over previous
#include <cuda_runtime.h>

#define NCOLS     16384
#define KSEL      655u
#define NTHREADS  512
#define NIT       8              // NCOLS / (NTHREADS*4)
#define CAP       3072u          // candidate buffer capacity
#define BCAP      256u           // boundary-bin buffer capacity

// shared layout (uint32 words)
#define OFF_CAND   0                          // CAP uint2 = 2*CAP words
#define OFF_HIST   (OFF_CAND + 2*CAP)         // 2048 bins
#define OFF_FLAGS  (OFF_HIST + 2048)          // 16384 bytes = 4096 words
#define OFF_BND    (OFF_FLAGS + 4096)         // BCAP uint2 = 512 words
#define OFF_GSUM   (OFF_BND + 2*BCAP)         // 64
#define OFF_BC     (OFF_GSUM + 64)            // 8 broadcast slots
#define OFF_CNT    (OFF_BC + 8)               // candidate counter
#define OFF_BCNT   (OFF_CNT + 1)              // boundary counter
#define SMEM_UINTS (OFF_BCNT + 1)
#define SMEM_BYTES (SMEM_UINTS * 4)

__device__ float g_boost[NCOLS];

__global__ void boost_kernel(const float* __restrict__ duty) {
    int i = blockIdx.x * blockDim.x + threadIdx.x;
    if (i < NCOLS) {
        const float target = 655.0f / 16384.0f;   // exact in f32
        float d = target - duty[i];               // same f32 op as reference
        g_boost[i] = (float)exp((double)d);       // correctly-rounded f32 exp
    }
}

// monotonic float->uint transform: order(key) == order(float)
__device__ __forceinline__ unsigned fkey(float f) {
    unsigned u = __float_as_uint(f);
    return u ^ (((unsigned)((int)u >> 31)) | 0x80000000u);
}

__device__ __forceinline__ uint4 keys4_at(const float4* __restrict__ xin,
                                          const float4* __restrict__ bfv, int i4) {
    float4 xv = __ldg(&xin[i4]);
    float4 bv = __ldg(&bfv[i4]);
    uint4 k;
    k.x = fkey(xv.x * bv.x);
    k.y = fkey(xv.y * bv.y);
    k.z = fkey(xv.z * bv.z);
    k.w = fkey(xv.w * bv.w);
    return k;
}

// Parallel "find bin where cumulative count from the top reaches `need`".
// Outputs: bc[0]=bin, bc[1]=remaining needed within bin, bc[5]=bin count.
__device__ __forceinline__ void scan_sel(unsigned* hist, int nbins, unsigned need,
                                         unsigned* gsum, unsigned* bc) {
    const int tid = threadIdx.x;
    const int gsz = nbins >> 6;
    if (tid == 0) { bc[6] = 0u; bc[7] = 0u; }
    if (tid < 64) {
        unsigned s = 0;
        for (int i = 0; i < gsz; i++) s += hist[tid * gsz + i];
        gsum[tid] = s;
    }
    __syncthreads();
    unsigned suf = 0;
    if (tid < 64) {
        for (int j = tid; j < 64; j++) suf += gsum[j];
    }
    __syncthreads();
    if (tid < 64) {
        gsum[tid] = suf;                       // group suffix sums
        if (suf >= need) atomicMax(&bc[6], 0x10000u | (unsigned)tid);
    }
    __syncthreads();
    const unsigned g = bc[6] & 0xFFFFu;        // largest group with suffix >= need
    const unsigned cumAbove = (g == 63u) ? 0u : gsum[g + 1];
    __syncthreads();
    const unsigned need2 = need - cumAbove;
    if (tid < gsz) {
        unsigned s2 = 0;
        for (int j = (int)g * gsz + tid; j < ((int)g + 1) * gsz; j++) s2 += hist[j];
        gsum[tid] = s2;                        // within-group bin suffix sums
        if (s2 >= need2) atomicMax(&bc[7], 0x10000u | (unsigned)tid);
    }
    __syncthreads();
    if (tid == 0) {
        unsigned bl = bc[7] & 0xFFFFu;
        unsigned b = g * (unsigned)gsz + bl;
        unsigned cum2 = (bl == (unsigned)(gsz - 1)) ? 0u : gsum[bl + 1];
        bc[0] = b;
        bc[1] = need2 - cum2;
        bc[5] = hist[b];
    }
    __syncthreads();
}

__global__ void __launch_bounds__(NTHREADS, 4)
kwinners_kernel(const float* __restrict__ x, float* __restrict__ out) {
    extern __shared__ unsigned sh[];
    uint2*         cand  = reinterpret_cast<uint2*>(sh + OFF_CAND);
    unsigned*      hist  = sh + OFF_HIST;
    unsigned char* flags = reinterpret_cast<unsigned char*>(sh + OFF_FLAGS);
    uint2*         bnd   = reinterpret_cast<uint2*>(sh + OFF_BND);
    unsigned*      gsum  = sh + OFF_GSUM;
    unsigned*      bc    = sh + OFF_BC;
    unsigned*      scnt  = sh + OFF_CNT;
    unsigned*      bcnt  = sh + OFF_BCNT;

    const int tid  = threadIdx.x;
    const int lane = tid & 31;
    const int row  = blockIdx.x;
    const float4* xin = reinterpret_cast<const float4*>(x + (size_t)row * NCOLS);
    const float4* bfv = reinterpret_cast<const float4*>(g_boost);
    float4* out4 = reinterpret_cast<float4*>(out + (size_t)row * NCOLS);

    const unsigned KMIN = fkey(0.8f);   // candidate threshold / linear-bin origin

    if (tid == 0) { *scnt = 0; *bcnt = 0; }
    #pragma unroll
    for (int i = 0; i < 4; i++) hist[tid + i * NTHREADS] = 0;
    {   // clear flags (16KB) with 128-bit stores
        uint4* f4 = reinterpret_cast<uint4*>(sh + OFF_FLAGS);
        const uint4 z = make_uint4(0, 0, 0, 0);
        f4[tid] = z;
        f4[tid + NTHREADS] = z;
    }
    __syncthreads();

    // ---- single full-N pass: load, key, compact candidates + inline histogram ----
    #pragma unroll
    for (int it = 0; it < NIT; it++) {
        int i4 = it * NTHREADS + tid;
        uint4 k = keys4_at(xin, bfv, i4);
        unsigned p0 = (k.x >= KMIN), p1 = (k.y >= KMIN);
        unsigned p2 = (k.z >= KMIN), p3 = (k.w >= KMIN);
        unsigned nc = p0 + p1 + p2 + p3;
        // warp-wide inclusive prefix of nc
        unsigned pre = nc;
        #pragma unroll
        for (int d = 1; d < 32; d <<= 1) {
            unsigned v = __shfl_up_sync(0xFFFFFFFFu, pre, d);
            if (lane >= d) pre += v;
        }
        unsigned tot = __shfl_sync(0xFFFFFFFFu, pre, 31);
        unsigned base = 0;
        if (lane == 31 && tot) base = atomicAdd(scnt, tot);
        base = __shfl_sync(0xFFFFFFFFu, base, 31);
        unsigned pos = base + pre - nc;
        unsigned bi = (unsigned)i4 * 4u;
        if (p0) { if (pos < CAP) { cand[pos] = make_uint2(k.x, bi + 0u);
                  atomicAdd(&hist[min(2047u, (k.x - KMIN) >> 15)], 1u); } pos++; }
        if (p1) { if (pos < CAP) { cand[pos] = make_uint2(k.y, bi + 1u);
                  atomicAdd(&hist[min(2047u, (k.y - KMIN) >> 15)], 1u); } pos++; }
        if (p2) { if (pos < CAP) { cand[pos] = make_uint2(k.z, bi + 2u);
                  atomicAdd(&hist[min(2047u, (k.z - KMIN) >> 15)], 1u); } pos++; }
        if (p3) { if (pos < CAP) { cand[pos] = make_uint2(k.w, bi + 3u);
                  atomicAdd(&hist[min(2047u, (k.w - KMIN) >> 15)], 1u); } pos++; }
    }
    __syncthreads();
    const unsigned total = *scnt;

    if (total >= KSEL && total <= CAP) {
        // ================= FAST PATH =================
        scan_sel(hist, 2048, KSEL, gsum, bc);
        const unsigned b1   = bc[0];
        const unsigned rem1 = bc[1];
        const unsigned Ecnt = bc[5];

        // classify: bin > b1 -> winner flag; bin == b1 -> boundary buffer
        for (unsigned i = tid; i < total; i += NTHREADS) {
            uint2 c = cand[i];
            unsigned bin = min(2047u, (c.x - KMIN) >> 15);
            if (bin > b1) {
                flags[c.y] = 1;
            } else if (bin == b1) {
                unsigned p = atomicAdd(bcnt, 1u);
                if (p < BCAP) bnd[p] = c;
            }
        }
        __syncthreads();

        if (Ecnt <= BCAP) {
            // exact rank within boundary bin: (key desc, index asc)
            if (tid < (int)Ecnt) {
                uint2 me = bnd[tid];
                unsigned rank = 0;
                for (unsigned j = 0; j < Ecnt; j++) {
                    uint2 o = bnd[j];
                    rank += (o.x > me.x) || (o.x == me.x && o.y < me.y);
                }
                if (rank < rem1) flags[me.y] = 1;
            }
        } else if (tid == 0) {
            // pathological boundary bin: exact serial selection (never for this data)
            unsigned need = rem1;
            while (need) {
                unsigned bestK = 0, bestI = 0xFFFFFFFFu, bj = 0;
                for (unsigned i = 0; i < total; i++) {
                    uint2 c = cand[i];
                    if (c.y & 0x80000000u) continue;
                    unsigned bin = min(2047u, (c.x - KMIN) >> 15);
                    if (bin != b1) continue;
                    if (c.x > bestK || (c.x == bestK && c.y < bestI)) {
                        bestK = c.x; bestI = c.y; bj = i;
                    }
                }
                flags[bestI] = 1;
                cand[bj].y |= 0x80000000u;
                need--;
            }
        }
        __syncthreads();

        // ---- single output pass from flags ----
        const uchar4* fl4 = reinterpret_cast<const uchar4*>(flags);
        #pragma unroll
        for (int it = 0; it < NIT; it++) {
            int i4 = it * NTHREADS + tid;
            uchar4 f = fl4[i4];
            float4 o;
            o.x = f.x ? 1.0f : 0.0f;
            o.y = f.y ? 1.0f : 0.0f;
            o.z = f.z ? 1.0f : 0.0f;
            o.w = f.w ? 1.0f : 0.0f;
            out4[i4] = o;
        }
    } else {
        // ================= FALLBACK: exact full radix, recompute keys =================
        #pragma unroll
        for (int i = 0; i < 4; i++) hist[tid + i * NTHREADS] = 0;
        __syncthreads();
        #pragma unroll
        for (int it = 0; it < NIT; it++) {
            uint4 k = keys4_at(xin, bfv, it * NTHREADS + tid);
            atomicAdd(&hist[k.x >> 21], 1u);
            atomicAdd(&hist[k.y >> 21], 1u);
            atomicAdd(&hist[k.z >> 21], 1u);
            atomicAdd(&hist[k.w >> 21], 1u);
        }
        __syncthreads();
        scan_sel(hist, 2048, KSEL, gsum, bc);
        const unsigned b1 = bc[0], rem1 = bc[1];
        #pragma unroll
        for (int i = 0; i < 4; i++) hist[tid + i * NTHREADS] = 0;
        __syncthreads();
        #pragma unroll
        for (int it = 0; it < NIT; it++) {
            uint4 k = keys4_at(xin, bfv, it * NTHREADS + tid);
            if ((k.x >> 21) == b1) atomicAdd(&hist[(k.x >> 10) & 2047u], 1u);
            if ((k.y >> 21) == b1) atomicAdd(&hist[(k.y >> 10) & 2047u], 1u);
            if ((k.z >> 21) == b1) atomicAdd(&hist[(k.z >> 10) & 2047u], 1u);
            if ((k.w >> 21) == b1) atomicAdd(&hist[(k.w >> 10) & 2047u], 1u);
        }
        __syncthreads();
        scan_sel(hist, 2048, rem1, gsum, bc);
        const unsigned b2 = bc[0], rem2 = bc[1];
        const unsigned pref21 = (b1 << 11) | b2;
        #pragma unroll
        for (int i = 0; i < 2; i++) hist[tid + i * NTHREADS] = 0;
        __syncthreads();
        #pragma unroll
        for (int it = 0; it < NIT; it++) {
            uint4 k = keys4_at(xin, bfv, it * NTHREADS + tid);
            if ((k.x >> 10) == pref21) atomicAdd(&hist[k.x & 1023u], 1u);
            if ((k.y >> 10) == pref21) atomicAdd(&hist[k.y & 1023u], 1u);
            if ((k.z >> 10) == pref21) atomicAdd(&hist[k.z & 1023u], 1u);
            if ((k.w >> 10) == pref21) atomicAdd(&hist[k.w & 1023u], 1u);
        }
        __syncthreads();
        scan_sel(hist, 1024, rem2, gsum, bc);
        const unsigned T    = (pref21 << 10) | bc[0];
        const unsigned rem3 = bc[1];
        const unsigned Ecnt = bc[5];

        if (rem3 != Ecnt) {
            if (tid == 0) *scnt = 0;
            __syncthreads();
            #pragma unroll
            for (int it = 0; it < NIT; it++) {
                int i4 = it * NTHREADS + tid;
                uint4 k = keys4_at(xin, bfv, i4);
                unsigned bi = (unsigned)i4 * 4u;
                if (k.x == T) { unsigned p = atomicAdd(scnt, 1u); if (p < CAP) cand[p].y = bi + 0u; }
                if (k.y == T) { unsigned p = atomicAdd(scnt, 1u); if (p < CAP) cand[p].y = bi + 1u; }
                if (k.z == T) { unsigned p = atomicAdd(scnt, 1u); if (p < CAP) cand[p].y = bi + 2u; }
                if (k.w == T) { unsigned p = atomicAdd(scnt, 1u); if (p < CAP) cand[p].y = bi + 3u; }
            }
            __syncthreads();
            if (tid == 0) {
                unsigned cnt = *scnt; if (cnt > CAP) cnt = CAP;
                unsigned Ith = 0;
                for (unsigned r = 0; r < rem3; r++) {
                    unsigned best = 0xFFFFFFFFu, bj = 0;
                    for (unsigned j = 0; j < cnt; j++)
                        if (cand[j].y < best) { best = cand[j].y; bj = j; }
                    cand[bj].y = 0xFFFFFFFFu;
                    Ith = best;
                }
                bc[3] = Ith;
            }
        } else if (tid == 0) {
            bc[3] = 0xFFFFFFFFu;
        }
        __syncthreads();
        const unsigned Ithr = bc[3];

        #pragma unroll
        for (int it = 0; it < NIT; it++) {
            int i4 = it * NTHREADS + tid;
            uint4 k = keys4_at(xin, bfv, i4);
            unsigned bi = (unsigned)i4 * 4u;
            float4 o;
            o.x = (k.x > T || (k.x == T && bi + 0u <= Ithr)) ? 1.0f : 0.0f;
            o.y = (k.y > T || (k.y == T && bi + 1u <= Ithr)) ? 1.0f : 0.0f;
            o.z = (k.z > T || (k.z == T && bi + 2u <= Ithr)) ? 1.0f : 0.0f;
            o.w = (k.w > T || (k.w == T && bi + 3u <= Ithr)) ? 1.0f : 0.0f;
            out4[i4] = o;
        }
    }
}

extern "C" void kernel_launch(void* const* d_in, const int* in_sizes, int n_in,
                              void* d_out, int out_size) {
    const float* x    = (const float*)d_in[0];
    const float* duty = (const float*)d_in[1];
    float* out        = (float*)d_out;
    int rows = in_sizes[0] / NCOLS;

    cudaFuncSetAttribute(kwinners_kernel,
                         cudaFuncAttributeMaxDynamicSharedMemorySize, SMEM_BYTES);

    boost_kernel<<<(NCOLS + 255) / 256, 256>>>(duty);
    kwinners_kernel<<<rows, NTHREADS, SMEM_BYTES>>>(x, out);
}

// round 4
// speedup vs baseline: 1.1705x; 1.0008x over previous
#include <cuda_runtime.h>

#define NCOLS     16384
#define KSEL      655u
#define NTHREADS  512
#define NIT       8              // NCOLS / (NTHREADS*4)
#define CAP       3072u          // candidate buffer capacity
#define BCAP      256u           // boundary-bin buffer capacity

// shared layout (uint32 words)
#define OFF_CAND   0                          // CAP uint2 = 2*CAP words
#define OFF_HIST   (OFF_CAND + 2*CAP)         // 2048 bins
#define OFF_FLAGS  (OFF_HIST + 2048)          // 16384 bytes = 4096 words
#define OFF_BND    (OFF_FLAGS + 4096)         // BCAP uint2 = 512 words
#define OFF_GSUM   (OFF_BND + 2*BCAP)         // 64
#define OFF_BC     (OFF_GSUM + 64)            // 8 broadcast slots
#define OFF_CNT    (OFF_BC + 8)               // candidate counter
#define OFF_BCNT   (OFF_CNT + 1)              // boundary counter
#define SMEM_UINTS (OFF_BCNT + 1)
#define SMEM_BYTES (SMEM_UINTS * 4)

__device__ float g_boost[NCOLS];

__global__ void boost_kernel(const float* __restrict__ duty) {
    int i = blockIdx.x * blockDim.x + threadIdx.x;
    if (i < NCOLS) {
        const float target = 655.0f / 16384.0f;   // exact in f32
        float d = target - duty[i];               // same f32 op as reference
        g_boost[i] = (float)exp((double)d);       // correctly-rounded f32 exp
    }
}

// monotonic float->uint transform: order(key) == order(float)
__device__ __forceinline__ unsigned fkey(float f) {
    unsigned u = __float_as_uint(f);
    return u ^ (((unsigned)((int)u >> 31)) | 0x80000000u);
}

__device__ __forceinline__ uint4 keys4_at(const float4* __restrict__ xin,
                                          const float4* __restrict__ bfv, int i4) {
    float4 xv = __ldg(&xin[i4]);
    float4 bv = __ldg(&bfv[i4]);
    uint4 k;
    k.x = fkey(xv.x * bv.x);
    k.y = fkey(xv.y * bv.y);
    k.z = fkey(xv.z * bv.z);
    k.w = fkey(xv.w * bv.w);
    return k;
}

// Parallel "find bin where cumulative count from the top reaches `need`".
// Outputs: bc[0]=bin, bc[1]=remaining needed within bin, bc[5]=bin count.
__device__ __forceinline__ void scan_sel(unsigned* hist, int nbins, unsigned need,
                                         unsigned* gsum, unsigned* bc) {
    const int tid = threadIdx.x;
    const int gsz = nbins >> 6;
    if (tid == 0) { bc[6] = 0u; bc[7] = 0u; }
    if (tid < 64) {
        unsigned s = 0;
        for (int i = 0; i < gsz; i++) s += hist[tid * gsz + i];
        gsum[tid] = s;
    }
    __syncthreads();
    unsigned suf = 0;
    if (tid < 64) {
        for (int j = tid; j < 64; j++) suf += gsum[j];
    }
    __syncthreads();
    if (tid < 64) {
        gsum[tid] = suf;                       // group suffix sums
        if (suf >= need) atomicMax(&bc[6], 0x10000u | (unsigned)tid);
    }
    __syncthreads();
    const unsigned g = bc[6] & 0xFFFFu;        // largest group with suffix >= need
    const unsigned cumAbove = (g == 63u) ? 0u : gsum[g + 1];
    __syncthreads();
    const unsigned need2 = need - cumAbove;
    if (tid < gsz) {
        unsigned s2 = 0;
        for (int j = (int)g * gsz + tid; j < ((int)g + 1) * gsz; j++) s2 += hist[j];
        gsum[tid] = s2;                        // within-group bin suffix sums
        if (s2 >= need2) atomicMax(&bc[7], 0x10000u | (unsigned)tid);
    }
    __syncthreads();
    if (tid == 0) {
        unsigned bl = bc[7] & 0xFFFFu;
        unsigned b = g * (unsigned)gsz + bl;
        unsigned cum2 = (bl == (unsigned)(gsz - 1)) ? 0u : gsum[bl + 1];
        bc[0] = b;
        bc[1] = need2 - cum2;
        bc[5] = hist[b];
    }
    __syncthreads();
}

__global__ void __launch_bounds__(NTHREADS, 4)
kwinners_kernel(const float* __restrict__ x, float* __restrict__ out) {
    extern __shared__ unsigned sh[];
    uint2*         cand  = reinterpret_cast<uint2*>(sh + OFF_CAND);
    unsigned*      hist  = sh + OFF_HIST;
    unsigned char* flags = reinterpret_cast<unsigned char*>(sh + OFF_FLAGS);
    uint2*         bnd   = reinterpret_cast<uint2*>(sh + OFF_BND);
    unsigned*      gsum  = sh + OFF_GSUM;
    unsigned*      bc    = sh + OFF_BC;
    unsigned*      scnt  = sh + OFF_CNT;
    unsigned*      bcnt  = sh + OFF_BCNT;

    const int tid  = threadIdx.x;
    const int lane = tid & 31;
    const int row  = blockIdx.x;
    const float4* xin = reinterpret_cast<const float4*>(x + (size_t)row * NCOLS);
    const float4* bfv = reinterpret_cast<const float4*>(g_boost);
    float4* out4 = reinterpret_cast<float4*>(out + (size_t)row * NCOLS);

    const unsigned KMIN = fkey(0.8f);   // candidate threshold / linear-bin origin

    if (tid == 0) { *scnt = 0; *bcnt = 0; }
    #pragma unroll
    for (int i = 0; i < 4; i++) hist[tid + i * NTHREADS] = 0;
    {   // clear flags (16KB) with 128-bit stores
        uint4* f4 = reinterpret_cast<uint4*>(sh + OFF_FLAGS);
        const uint4 z = make_uint4(0, 0, 0, 0);
        f4[tid] = z;
        f4[tid + NTHREADS] = z;
    }
    __syncthreads();

    // ---- single full-N pass: load, key, compact candidates + inline histogram ----
    #pragma unroll
    for (int it = 0; it < NIT; it++) {
        int i4 = it * NTHREADS + tid;
        uint4 k = keys4_at(xin, bfv, i4);
        unsigned p0 = (k.x >= KMIN), p1 = (k.y >= KMIN);
        unsigned p2 = (k.z >= KMIN), p3 = (k.w >= KMIN);
        unsigned nc = p0 + p1 + p2 + p3;
        // warp-wide inclusive prefix of nc
        unsigned pre = nc;
        #pragma unroll
        for (int d = 1; d < 32; d <<= 1) {
            unsigned v = __shfl_up_sync(0xFFFFFFFFu, pre, d);
            if (lane >= d) pre += v;
        }
        unsigned tot = __shfl_sync(0xFFFFFFFFu, pre, 31);
        unsigned base = 0;
        if (lane == 31 && tot) base = atomicAdd(scnt, tot);
        base = __shfl_sync(0xFFFFFFFFu, base, 31);
        unsigned pos = base + pre - nc;
        unsigned bi = (unsigned)i4 * 4u;
        if (p0) { if (pos < CAP) { cand[pos] = make_uint2(k.x, bi + 0u);
                  atomicAdd(&hist[min(2047u, (k.x - KMIN) >> 15)], 1u); } pos++; }
        if (p1) { if (pos < CAP) { cand[pos] = make_uint2(k.y, bi + 1u);
                  atomicAdd(&hist[min(2047u, (k.y - KMIN) >> 15)], 1u); } pos++; }
        if (p2) { if (pos < CAP) { cand[pos] = make_uint2(k.z, bi + 2u);
                  atomicAdd(&hist[min(2047u, (k.z - KMIN) >> 15)], 1u); } pos++; }
        if (p3) { if (pos < CAP) { cand[pos] = make_uint2(k.w, bi + 3u);
                  atomicAdd(&hist[min(2047u, (k.w - KMIN) >> 15)], 1u); } pos++; }
    }
    __syncthreads();
    const unsigned total = *scnt;

    if (total >= KSEL && total <= CAP) {
        // ================= FAST PATH =================
        scan_sel(hist, 2048, KSEL, gsum, bc);
        const unsigned b1   = bc[0];
        const unsigned rem1 = bc[1];
        const unsigned Ecnt = bc[5];

        // classify: bin > b1 -> winner flag; bin == b1 -> boundary buffer
        for (unsigned i = tid; i < total; i += NTHREADS) {
            uint2 c = cand[i];
            unsigned bin = min(2047u, (c.x - KMIN) >> 15);
            if (bin > b1) {
                flags[c.y] = 1;
            } else if (bin == b1) {
                unsigned p = atomicAdd(bcnt, 1u);
                if (p < BCAP) bnd[p] = c;
            }
        }
        __syncthreads();

        if (Ecnt <= BCAP) {
            // exact rank within boundary bin: (key desc, index asc)
            if (tid < (int)Ecnt) {
                uint2 me = bnd[tid];
                unsigned rank = 0;
                for (unsigned j = 0; j < Ecnt; j++) {
                    uint2 o = bnd[j];
                    rank += (o.x > me.x) || (o.x == me.x && o.y < me.y);
                }
                if (rank < rem1) flags[me.y] = 1;
            }
        } else if (tid == 0) {
            // pathological boundary bin: exact serial selection (never for this data)
            unsigned need = rem1;
            while (need) {
                unsigned bestK = 0, bestI = 0xFFFFFFFFu, bj = 0;
                for (unsigned i = 0; i < total; i++) {
                    uint2 c = cand[i];
                    if (c.y & 0x80000000u) continue;
                    unsigned bin = min(2047u, (c.x - KMIN) >> 15);
                    if (bin != b1) continue;
                    if (c.x > bestK || (c.x == bestK && c.y < bestI)) {
                        bestK = c.x; bestI = c.y; bj = i;
                    }
                }
                flags[bestI] = 1;
                cand[bj].y |= 0x80000000u;
                need--;
            }
        }
        __syncthreads();

        // ---- single output pass from flags ----
        const uchar4* fl4 = reinterpret_cast<const uchar4*>(flags);
        #pragma unroll
        for (int it = 0; it < NIT; it++) {
            int i4 = it * NTHREADS + tid;
            uchar4 f = fl4[i4];
            float4 o;
            o.x = f.x ? 1.0f : 0.0f;
            o.y = f.y ? 1.0f : 0.0f;
            o.z = f.z ? 1.0f : 0.0f;
            o.w = f.w ? 1.0f : 0.0f;
            out4[i4] = o;
        }
    } else {
        // ================= FALLBACK: exact full radix, recompute keys =================
        #pragma unroll
        for (int i = 0; i < 4; i++) hist[tid + i * NTHREADS] = 0;
        __syncthreads();
        #pragma unroll
        for (int it = 0; it < NIT; it++) {
            uint4 k = keys4_at(xin, bfv, it * NTHREADS + tid);
            atomicAdd(&hist[k.x >> 21], 1u);
            atomicAdd(&hist[k.y >> 21], 1u);
            atomicAdd(&hist[k.z >> 21], 1u);
            atomicAdd(&hist[k.w >> 21], 1u);
        }
        __syncthreads();
        scan_sel(hist, 2048, KSEL, gsum, bc);
        const unsigned b1 = bc[0], rem1 = bc[1];
        #pragma unroll
        for (int i = 0; i < 4; i++) hist[tid + i * NTHREADS] = 0;
        __syncthreads();
        #pragma unroll
        for (int it = 0; it < NIT; it++) {
            uint4 k = keys4_at(xin, bfv, it * NTHREADS + tid);
            if ((k.x >> 21) == b1) atomicAdd(&hist[(k.x >> 10) & 2047u], 1u);
            if ((k.y >> 21) == b1) atomicAdd(&hist[(k.y >> 10) & 2047u], 1u);
            if ((k.z >> 21) == b1) atomicAdd(&hist[(k.z >> 10) & 2047u], 1u);
            if ((k.w >> 21) == b1) atomicAdd(&hist[(k.w >> 10) & 2047u], 1u);
        }
        __syncthreads();
        scan_sel(hist, 2048, rem1, gsum, bc);
        const unsigned b2 = bc[0], rem2 = bc[1];
        const unsigned pref21 = (b1 << 11) | b2;
        #pragma unroll
        for (int i = 0; i < 2; i++) hist[tid + i * NTHREADS] = 0;
        __syncthreads();
        #pragma unroll
        for (int it = 0; it < NIT; it++) {
            uint4 k = keys4_at(xin, bfv, it * NTHREADS + tid);
            if ((k.x >> 10) == pref21) atomicAdd(&hist[k.x & 1023u], 1u);
            if ((k.y >> 10) == pref21) atomicAdd(&hist[k.y & 1023u], 1u);
            if ((k.z >> 10) == pref21) atomicAdd(&hist[k.z & 1023u], 1u);
            if ((k.w >> 10) == pref21) atomicAdd(&hist[k.w & 1023u], 1u);
        }
        __syncthreads();
        scan_sel(hist, 1024, rem2, gsum, bc);
        const unsigned T    = (pref21 << 10) | bc[0];
        const unsigned rem3 = bc[1];
        const unsigned Ecnt = bc[5];

        if (rem3 != Ecnt) {
            if (tid == 0) *scnt = 0;
            __syncthreads();
            #pragma unroll
            for (int it = 0; it < NIT; it++) {
                int i4 = it * NTHREADS + tid;
                uint4 k = keys4_at(xin, bfv, i4);
                unsigned bi = (unsigned)i4 * 4u;
                if (k.x == T) { unsigned p = atomicAdd(scnt, 1u); if (p < CAP) cand[p].y = bi + 0u; }
                if (k.y == T) { unsigned p = atomicAdd(scnt, 1u); if (p < CAP) cand[p].y = bi + 1u; }
                if (k.z == T) { unsigned p = atomicAdd(scnt, 1u); if (p < CAP) cand[p].y = bi + 2u; }
                if (k.w == T) { unsigned p = atomicAdd(scnt, 1u); if (p < CAP) cand[p].y = bi + 3u; }
            }
            __syncthreads();
            if (tid == 0) {
                unsigned cnt = *scnt; if (cnt > CAP) cnt = CAP;
                unsigned Ith = 0;
                for (unsigned r = 0; r < rem3; r++) {
                    unsigned best = 0xFFFFFFFFu, bj = 0;
                    for (unsigned j = 0; j < cnt; j++)
                        if (cand[j].y < best) { best = cand[j].y; bj = j; }
                    cand[bj].y = 0xFFFFFFFFu;
                    Ith = best;
                }
                bc[3] = Ith;
            }
        } else if (tid == 0) {
            bc[3] = 0xFFFFFFFFu;
        }
        __syncthreads();
        const unsigned Ithr = bc[3];

        #pragma unroll
        for (int it = 0; it < NIT; it++) {
            int i4 = it * NTHREADS + tid;
            uint4 k = keys4_at(xin, bfv, i4);
            unsigned bi = (unsigned)i4 * 4u;
            float4 o;
            o.x = (k.x > T || (k.x == T && bi + 0u <= Ithr)) ? 1.0f : 0.0f;
            o.y = (k.y > T || (k.y == T && bi + 1u <= Ithr)) ? 1.0f : 0.0f;
            o.z = (k.z > T || (k.z == T && bi + 2u <= Ithr)) ? 1.0f : 0.0f;
            o.w = (k.w > T || (k.w == T && bi + 3u <= Ithr)) ? 1.0f : 0.0f;
            out4[i4] = o;
        }
    }
}

extern "C" void kernel_launch(void* const* d_in, const int* in_sizes, int n_in,
                              void* d_out, int out_size) {
    const float* x    = (const float*)d_in[0];
    const float* duty = (const float*)d_in[1];
    float* out        = (float*)d_out;
    int rows = in_sizes[0] / NCOLS;

    cudaFuncSetAttribute(kwinners_kernel,
                         cudaFuncAttributeMaxDynamicSharedMemorySize, SMEM_BYTES);

    boost_kernel<<<(NCOLS + 255) / 256, 256>>>(duty);
    kwinners_kernel<<<rows, NTHREADS, SMEM_BYTES>>>(x, out);
}

// round 5
// speedup vs baseline: 1.2822x; 1.0954x over previous
#include <cuda_runtime.h>

#define NCOLS     16384
#define KSEL      655u
#define NTHREADS  512
#define NIT       8              // NCOLS / (NTHREADS*4)
#define CAP       3072u          // candidate buffer capacity
#define BCAP      512u           // boundary-bin buffer capacity

// shared layout (uint32 words)
#define OFF_CAND   0                       // CAP packed candidates (u32)
#define OFF_HIST   (OFF_CAND + CAP)        // 2048 bins
#define OFF_BMASK  (OFF_HIST + 2048)       // 512 words = 16384 bits
#define OFF_BIDX   (OFF_BMASK + 512)       // BCAP boundary indices
#define OFF_BKEY   (OFF_BIDX + BCAP)       // BCAP boundary exact keys
#define OFF_GSUM   (OFF_BKEY + BCAP)       // 64
#define OFF_BC     (OFF_GSUM + 64)         // 8 broadcast slots
#define OFF_CNT    (OFF_BC + 8)            // candidate counter
#define OFF_BCNT   (OFF_CNT + 1)           // boundary counter
#define SMEM_UINTS (OFF_BCNT + 1)
#define SMEM_BYTES (SMEM_UINTS * 4)

// fkey(0.8f) = (0x3F4CCCCD | 0x80000000) = 0xBF4CCCCD, aligned down to 2^15:
#define KMIN 0xBF4C8000u

__device__ float g_boost[NCOLS];

__global__ void boost_kernel(const float* __restrict__ duty) {
    int i = blockIdx.x * blockDim.x + threadIdx.x;
    if (i < NCOLS) {
        const float target = 655.0f / 16384.0f;   // exact in f32
        float d = target - duty[i];               // same f32 op as reference
        g_boost[i] = (float)exp((double)d);       // correctly-rounded f32 exp
    }
}

// monotonic float->uint transform: order(key) == order(float)
__device__ __forceinline__ unsigned fkey(float f) {
    unsigned u = __float_as_uint(f);
    return u ^ (((unsigned)((int)u >> 31)) | 0x80000000u);
}

__device__ __forceinline__ uint4 keys4_at(const float4* __restrict__ xin,
                                          const float4* __restrict__ bfv, int i4) {
    float4 xv = __ldg(&xin[i4]);
    float4 bv = __ldg(&bfv[i4]);
    uint4 k;
    k.x = fkey(xv.x * bv.x);
    k.y = fkey(xv.y * bv.y);
    k.z = fkey(xv.z * bv.z);
    k.w = fkey(xv.w * bv.w);
    return k;
}

// Parallel "find bin where cumulative count from the top reaches `need`".
// Outputs: bc[0]=bin, bc[1]=remaining needed within bin, bc[5]=bin count.
__device__ __forceinline__ void scan_sel(unsigned* hist, int nbins, unsigned need,
                                         unsigned* gsum, unsigned* bc) {
    const int tid = threadIdx.x;
    const int gsz = nbins >> 6;
    if (tid == 0) { bc[6] = 0u; bc[7] = 0u; }
    if (tid < 64) {
        unsigned s = 0;
        for (int i = 0; i < gsz; i++) s += hist[tid * gsz + i];
        gsum[tid] = s;
    }
    __syncthreads();
    unsigned suf = 0;
    if (tid < 64) {
        for (int j = tid; j < 64; j++) suf += gsum[j];
    }
    __syncthreads();
    if (tid < 64) {
        gsum[tid] = suf;                       // group suffix sums
        if (suf >= need) atomicMax(&bc[6], 0x10000u | (unsigned)tid);
    }
    __syncthreads();
    const unsigned g = bc[6] & 0xFFFFu;        // largest group with suffix >= need
    const unsigned cumAbove = (g == 63u) ? 0u : gsum[g + 1];
    __syncthreads();
    const unsigned need2 = need - cumAbove;
    if (tid < gsz) {
        unsigned s2 = 0;
        for (int j = (int)g * gsz + tid; j < ((int)g + 1) * gsz; j++) s2 += hist[j];
        gsum[tid] = s2;                        // within-group bin suffix sums
        if (s2 >= need2) atomicMax(&bc[7], 0x10000u | (unsigned)tid);
    }
    __syncthreads();
    if (tid == 0) {
        unsigned bl = bc[7] & 0xFFFFu;
        unsigned b = g * (unsigned)gsz + bl;
        unsigned cum2 = (bl == (unsigned)(gsz - 1)) ? 0u : gsum[bl + 1];
        bc[0] = b;
        bc[1] = need2 - cum2;
        bc[5] = hist[b];
    }
    __syncthreads();
}

__global__ void __launch_bounds__(NTHREADS, 4)
kwinners_kernel(const float* __restrict__ x, float* __restrict__ out) {
    extern __shared__ unsigned sh[];
    unsigned* cand  = sh + OFF_CAND;    // packed: (key & 0xFFFFC000) | idx14
    unsigned* hist  = sh + OFF_HIST;
    unsigned* bmask = sh + OFF_BMASK;
    unsigned* bidx  = sh + OFF_BIDX;
    unsigned* bkey  = sh + OFF_BKEY;
    unsigned* gsum  = sh + OFF_GSUM;
    unsigned* bc    = sh + OFF_BC;
    unsigned* scnt  = sh + OFF_CNT;
    unsigned* bcnt  = sh + OFF_BCNT;

    const int tid  = threadIdx.x;
    const int lane = tid & 31;
    const int row  = blockIdx.x;
    const float*  xrow = x + (size_t)row * NCOLS;
    const float4* xin  = reinterpret_cast<const float4*>(xrow);
    const float4* bfv  = reinterpret_cast<const float4*>(g_boost);
    float4* out4 = reinterpret_cast<float4*>(out + (size_t)row * NCOLS);

    if (tid == 0) { *scnt = 0; *bcnt = 0; }
    // clear hist (2048 words) + bmask (512 words)
    reinterpret_cast<uint4*>(hist)[tid] = make_uint4(0, 0, 0, 0);
    if (tid < 128) reinterpret_cast<uint4*>(bmask)[tid] = make_uint4(0, 0, 0, 0);
    __syncthreads();

    // ---- single full-N pass: load, key, ballot-compact + inline histogram ----
    #pragma unroll
    for (int it = 0; it < NIT; it++) {
        int i4 = it * NTHREADS + tid;
        float4 xv = __ldcs(&xin[i4]);
        float4 bv = __ldg(&bfv[i4]);
        unsigned k0 = fkey(xv.x * bv.x);
        unsigned k1 = fkey(xv.y * bv.y);
        unsigned k2 = fkey(xv.z * bv.z);
        unsigned k3 = fkey(xv.w * bv.w);
        bool p0 = k0 >= KMIN, p1 = k1 >= KMIN, p2 = k2 >= KMIN, p3 = k3 >= KMIN;

        unsigned m0 = __ballot_sync(0xFFFFFFFFu, p0);
        unsigned m1 = __ballot_sync(0xFFFFFFFFu, p1);
        unsigned m2 = __ballot_sync(0xFFFFFFFFu, p2);
        unsigned m3 = __ballot_sync(0xFFFFFFFFu, p3);
        unsigned c0 = __popc(m0);
        unsigned c01 = c0 + __popc(m1);
        unsigned c012 = c01 + __popc(m2);
        unsigned tot = c012 + __popc(m3);

        unsigned base = 0;
        if (lane == 0) base = atomicAdd(scnt, tot);
        base = __shfl_sync(0xFFFFFFFFu, base, 0);

        unsigned lt = (1u << lane) - 1u;
        unsigned bi = (unsigned)i4 * 4u;
        if (p0) { unsigned p = base + __popc(m0 & lt);
                  if (p < CAP) { cand[p] = (k0 & 0xFFFFC000u) | (bi + 0u);
                                 atomicAdd(&hist[min(2047u, (k0 - KMIN) >> 15)], 1u); } }
        if (p1) { unsigned p = base + c0 + __popc(m1 & lt);
                  if (p < CAP) { cand[p] = (k1 & 0xFFFFC000u) | (bi + 1u);
                                 atomicAdd(&hist[min(2047u, (k1 - KMIN) >> 15)], 1u); } }
        if (p2) { unsigned p = base + c01 + __popc(m2 & lt);
                  if (p < CAP) { cand[p] = (k2 & 0xFFFFC000u) | (bi + 2u);
                                 atomicAdd(&hist[min(2047u, (k2 - KMIN) >> 15)], 1u); } }
        if (p3) { unsigned p = base + c012 + __popc(m3 & lt);
                  if (p < CAP) { cand[p] = (k3 & 0xFFFFC000u) | (bi + 3u);
                                 atomicAdd(&hist[min(2047u, (k3 - KMIN) >> 15)], 1u); } }
    }
    __syncthreads();
    const unsigned total = *scnt;

    bool fast = (total >= KSEL && total <= CAP);
    unsigned b1 = 0, rem1 = 0, Ecnt = 0;
    if (fast) {
        scan_sel(hist, 2048, KSEL, gsum, bc);
        b1 = bc[0]; rem1 = bc[1]; Ecnt = bc[5];
        if (Ecnt > BCAP) fast = false;        // pathological: exact fallback below
    }

    if (fast) {
        // ---- classify: bin > b1 -> winner bit; bin == b1 -> boundary ----
        for (unsigned i = tid; i < total; i += NTHREADS) {
            unsigned c = cand[i];
            unsigned bin = min(2047u, (c - KMIN) >> 15);   // idx bits don't reach bit 15
            if (bin > b1) {
                unsigned idx = c & 0x3FFFu;
                atomicOr(&bmask[idx >> 5], 1u << (idx & 31u));
            } else if (bin == b1) {
                unsigned p = atomicAdd(bcnt, 1u);
                bidx[p] = c & 0x3FFFu;                      // p < Ecnt <= BCAP
            }
        }
        __syncthreads();

        // ---- boundary: recompute exact keys, rank (key desc, index asc) ----
        if (tid < (int)Ecnt) {
            unsigned idx = bidx[tid];
            bkey[tid] = fkey(__ldg(&xrow[idx]) * __ldg(&g_boost[idx]));
        }
        __syncthreads();
        if (tid < (int)Ecnt) {
            unsigned mk = bkey[tid], mi = bidx[tid];
            unsigned rank = 0;
            for (unsigned j = 0; j < Ecnt; j++) {
                unsigned ok = bkey[j];
                rank += (ok > mk) || (ok == mk && bidx[j] < mi);
            }
            if (rank < rem1) atomicOr(&bmask[mi >> 5], 1u << (mi & 31u));
        }
        __syncthreads();

        // ---- single output pass from bitmask ----
        #pragma unroll
        for (int it = 0; it < NIT; it++) {
            int i4 = it * NTHREADS + tid;
            unsigned w = bmask[i4 >> 3];
            unsigned f = (w >> ((i4 & 7) * 4)) & 0xFu;
            float4 o;
            o.x = (f & 1u) ? 1.0f : 0.0f;
            o.y = (f & 2u) ? 1.0f : 0.0f;
            o.z = (f & 4u) ? 1.0f : 0.0f;
            o.w = (f & 8u) ? 1.0f : 0.0f;
            __stcs(&out4[i4], o);
        }
    } else {
        // ================= FALLBACK: exact full 3-pass radix, recompute keys =================
        reinterpret_cast<uint4*>(hist)[tid] = make_uint4(0, 0, 0, 0);
        __syncthreads();
        #pragma unroll
        for (int it = 0; it < NIT; it++) {
            uint4 k = keys4_at(xin, bfv, it * NTHREADS + tid);
            atomicAdd(&hist[k.x >> 21], 1u);
            atomicAdd(&hist[k.y >> 21], 1u);
            atomicAdd(&hist[k.z >> 21], 1u);
            atomicAdd(&hist[k.w >> 21], 1u);
        }
        __syncthreads();
        scan_sel(hist, 2048, KSEL, gsum, bc);
        const unsigned fb1 = bc[0], frem1 = bc[1];
        reinterpret_cast<uint4*>(hist)[tid] = make_uint4(0, 0, 0, 0);
        __syncthreads();
        #pragma unroll
        for (int it = 0; it < NIT; it++) {
            uint4 k = keys4_at(xin, bfv, it * NTHREADS + tid);
            if ((k.x >> 21) == fb1) atomicAdd(&hist[(k.x >> 10) & 2047u], 1u);
            if ((k.y >> 21) == fb1) atomicAdd(&hist[(k.y >> 10) & 2047u], 1u);
            if ((k.z >> 21) == fb1) atomicAdd(&hist[(k.z >> 10) & 2047u], 1u);
            if ((k.w >> 21) == fb1) atomicAdd(&hist[(k.w >> 10) & 2047u], 1u);
        }
        __syncthreads();
        scan_sel(hist, 2048, frem1, gsum, bc);
        const unsigned fb2 = bc[0], frem2 = bc[1];
        const unsigned pref21 = (fb1 << 11) | fb2;
        if (tid < 256) reinterpret_cast<uint4*>(hist)[tid] = make_uint4(0, 0, 0, 0);
        __syncthreads();
        #pragma unroll
        for (int it = 0; it < NIT; it++) {
            uint4 k = keys4_at(xin, bfv, it * NTHREADS + tid);
            if ((k.x >> 10) == pref21) atomicAdd(&hist[k.x & 1023u], 1u);
            if ((k.y >> 10) == pref21) atomicAdd(&hist[k.y & 1023u], 1u);
            if ((k.z >> 10) == pref21) atomicAdd(&hist[k.z & 1023u], 1u);
            if ((k.w >> 10) == pref21) atomicAdd(&hist[k.w & 1023u], 1u);
        }
        __syncthreads();
        scan_sel(hist, 1024, frem2, gsum, bc);
        const unsigned T    = (pref21 << 10) | bc[0];
        const unsigned rem3 = bc[1];
        const unsigned EcntF = bc[5];

        if (rem3 != EcntF) {
            if (tid == 0) *scnt = 0;
            __syncthreads();
            #pragma unroll
            for (int it = 0; it < NIT; it++) {
                int i4 = it * NTHREADS + tid;
                uint4 k = keys4_at(xin, bfv, i4);
                unsigned bi = (unsigned)i4 * 4u;
                if (k.x == T) { unsigned p = atomicAdd(scnt, 1u); if (p < CAP) cand[p] = bi + 0u; }
                if (k.y == T) { unsigned p = atomicAdd(scnt, 1u); if (p < CAP) cand[p] = bi + 1u; }
                if (k.z == T) { unsigned p = atomicAdd(scnt, 1u); if (p < CAP) cand[p] = bi + 2u; }
                if (k.w == T) { unsigned p = atomicAdd(scnt, 1u); if (p < CAP) cand[p] = bi + 3u; }
            }
            __syncthreads();
            if (tid == 0) {
                unsigned cnt = *scnt; if (cnt > CAP) cnt = CAP;
                unsigned Ith = 0;
                for (unsigned r = 0; r < rem3; r++) {
                    unsigned best = 0xFFFFFFFFu, bj = 0;
                    for (unsigned j = 0; j < cnt; j++)
                        if (cand[j] < best) { best = cand[j]; bj = j; }
                    cand[bj] = 0xFFFFFFFFu;
                    Ith = best;
                }
                bc[3] = Ith;
            }
        } else if (tid == 0) {
            bc[3] = 0xFFFFFFFFu;
        }
        __syncthreads();
        const unsigned Ithr = bc[3];

        #pragma unroll
        for (int it = 0; it < NIT; it++) {
            int i4 = it * NTHREADS + tid;
            uint4 k = keys4_at(xin, bfv, i4);
            unsigned bi = (unsigned)i4 * 4u;
            float4 o;
            o.x = (k.x > T || (k.x == T && bi + 0u <= Ithr)) ? 1.0f : 0.0f;
            o.y = (k.y > T || (k.y == T && bi + 1u <= Ithr)) ? 1.0f : 0.0f;
            o.z = (k.z > T || (k.z == T && bi + 2u <= Ithr)) ? 1.0f : 0.0f;
            o.w = (k.w > T || (k.w == T && bi + 3u <= Ithr)) ? 1.0f : 0.0f;
            out4[i4] = o;
        }
    }
}

extern "C" void kernel_launch(void* const* d_in, const int* in_sizes, int n_in,
                              void* d_out, int out_size) {
    const float* x    = (const float*)d_in[0];
    const float* duty = (const float*)d_in[1];
    float* out        = (float*)d_out;
    int rows = in_sizes[0] / NCOLS;

    cudaFuncSetAttribute(kwinners_kernel,
                         cudaFuncAttributeMaxDynamicSharedMemorySize, SMEM_BYTES);

    boost_kernel<<<(NCOLS + 255) / 256, 256>>>(duty);
    kwinners_kernel<<<rows, NTHREADS, SMEM_BYTES>>>(x, out);
}

// round 6
// speedup vs baseline: 1.3274x; 1.0352x over previous
#include <cuda_runtime.h>

#define NCOLS     16384
#define KSEL      655u
#define NTHREADS  512
#define NIT       8              // NCOLS / (NTHREADS*4)
#define CAP       3072u          // candidate buffer capacity
#define BCAP      512u           // boundary-bin buffer capacity

// shared layout (uint32 words)
#define OFF_CAND   0                       // CAP packed candidates (u32)
#define OFF_HIST   (OFF_CAND + CAP)        // 2048 bins
#define OFF_BMASK  (OFF_HIST + 2048)       // 512 words = 16384 bits
#define OFF_BIDX   (OFF_BMASK + 512)       // BCAP boundary indices
#define OFF_BKEY   (OFF_BIDX + BCAP)       // BCAP boundary exact keys
#define OFF_GSUM   (OFF_BKEY + BCAP)       // 64
#define OFF_BC     (OFF_GSUM + 64)         // 8 broadcast slots
#define OFF_CNT    (OFF_BC + 8)            // candidate counter
#define OFF_BCNT   (OFF_CNT + 1)           // boundary counter
#define SMEM_UINTS (OFF_BCNT + 1)
#define SMEM_BYTES (SMEM_UINTS * 4)

// fkey(0.8f) = 0xBF4CCCCD, aligned down to 2^15:
#define KMIN 0xBF4C8000u
// the float whose fkey is exactly KMIN: 0x3F4C8000 = 0.798828125
// for ANY float v:  (v >= FTHR)  <=>  (fkey(v) >= KMIN)
#define FTHR 0.798828125f

__device__ float g_boost[NCOLS];

__global__ void boost_kernel(const float* __restrict__ duty) {
    int i = blockIdx.x * blockDim.x + threadIdx.x;
    if (i < NCOLS) {
        const float target = 655.0f / 16384.0f;   // exact in f32
        float d = target - duty[i];               // same f32 op as reference
        g_boost[i] = (float)exp((double)d);       // correctly-rounded f32 exp
    }
}

// monotonic float->uint transform: order(key) == order(float)
__device__ __forceinline__ unsigned fkey(float f) {
    unsigned u = __float_as_uint(f);
    return u ^ (((unsigned)((int)u >> 31)) | 0x80000000u);
}

// fkey for values known positive (candidates are >= FTHR > 0)
__device__ __forceinline__ unsigned fkey_pos(float f) {
    return __float_as_uint(f) | 0x80000000u;
}

__device__ __forceinline__ uint4 keys4_at(const float4* __restrict__ xin,
                                          const float4* __restrict__ bfv, int i4) {
    float4 xv = __ldg(&xin[i4]);
    float4 bv = __ldg(&bfv[i4]);
    uint4 k;
    k.x = fkey(xv.x * bv.x);
    k.y = fkey(xv.y * bv.y);
    k.z = fkey(xv.z * bv.z);
    k.w = fkey(xv.w * bv.w);
    return k;
}

// Parallel "find bin where cumulative count from the top reaches `need`".
// Outputs: bc[0]=bin, bc[1]=remaining needed within bin, bc[5]=bin count.
__device__ __forceinline__ void scan_sel(unsigned* hist, int nbins, unsigned need,
                                         unsigned* gsum, unsigned* bc) {
    const int tid = threadIdx.x;
    const int gsz = nbins >> 6;
    if (tid == 0) { bc[6] = 0u; bc[7] = 0u; }
    if (tid < 64) {
        unsigned s = 0;
        for (int i = 0; i < gsz; i++) s += hist[tid * gsz + i];
        gsum[tid] = s;
    }
    __syncthreads();
    unsigned suf = 0;
    if (tid < 64) {
        for (int j = tid; j < 64; j++) suf += gsum[j];
    }
    __syncthreads();
    if (tid < 64) {
        gsum[tid] = suf;                       // group suffix sums
        if (suf >= need) atomicMax(&bc[6], 0x10000u | (unsigned)tid);
    }
    __syncthreads();
    const unsigned g = bc[6] & 0xFFFFu;        // largest group with suffix >= need
    const unsigned cumAbove = (g == 63u) ? 0u : gsum[g + 1];
    __syncthreads();
    const unsigned need2 = need - cumAbove;
    if (tid < gsz) {
        unsigned s2 = 0;
        for (int j = (int)g * gsz + tid; j < ((int)g + 1) * gsz; j++) s2 += hist[j];
        gsum[tid] = s2;                        // within-group bin suffix sums
        if (s2 >= need2) atomicMax(&bc[7], 0x10000u | (unsigned)tid);
    }
    __syncthreads();
    if (tid == 0) {
        unsigned bl = bc[7] & 0xFFFFu;
        unsigned b = g * (unsigned)gsz + bl;
        unsigned cum2 = (bl == (unsigned)(gsz - 1)) ? 0u : gsum[bl + 1];
        bc[0] = b;
        bc[1] = need2 - cum2;
        bc[5] = hist[b];
    }
    __syncthreads();
}

__global__ void __launch_bounds__(NTHREADS, 4)
kwinners_kernel(const float* __restrict__ x, float* __restrict__ out) {
    extern __shared__ unsigned sh[];
    unsigned* cand  = sh + OFF_CAND;    // packed: (key & 0xFFFFC000) | idx14
    unsigned* hist  = sh + OFF_HIST;
    unsigned* bmask = sh + OFF_BMASK;
    unsigned* bidx  = sh + OFF_BIDX;
    unsigned* bkey  = sh + OFF_BKEY;
    unsigned* gsum  = sh + OFF_GSUM;
    unsigned* bc    = sh + OFF_BC;
    unsigned* scnt  = sh + OFF_CNT;
    unsigned* bcnt  = sh + OFF_BCNT;

    const int tid  = threadIdx.x;
    const int row  = blockIdx.x;
    const float*  xrow = x + (size_t)row * NCOLS;
    const float4* xin  = reinterpret_cast<const float4*>(xrow);
    const float4* bfv  = reinterpret_cast<const float4*>(g_boost);
    float4* out4 = reinterpret_cast<float4*>(out + (size_t)row * NCOLS);

    if (tid == 0) { *scnt = 0; *bcnt = 0; }
    // clear hist (2048 words) + bmask (512 words)
    reinterpret_cast<uint4*>(hist)[tid] = make_uint4(0, 0, 0, 0);
    if (tid < 128) reinterpret_cast<uint4*>(bmask)[tid] = make_uint4(0, 0, 0, 0);
    __syncthreads();

    // ---- single full-N pass: load, float-compare, compact + inline histogram ----
    #pragma unroll
    for (int it = 0; it < NIT; it++) {
        int i4 = it * NTHREADS + tid;
        float4 xv = __ldcs(&xin[i4]);
        float4 bv = __ldg(&bfv[i4]);
        float v0 = xv.x * bv.x;
        float v1 = xv.y * bv.y;
        float v2 = xv.z * bv.z;
        float v3 = xv.w * bv.w;
        bool p0 = v0 >= FTHR, p1 = v1 >= FTHR, p2 = v2 >= FTHR, p3 = v3 >= FTHR;
        unsigned nc = (unsigned)p0 + (unsigned)p1 + (unsigned)p2 + (unsigned)p3;
        if (nc) {
            unsigned pos = atomicAdd(scnt, nc);
            unsigned bi = (unsigned)i4 * 4u;
            if (p0) { unsigned k = fkey_pos(v0);
                      if (pos < CAP) { cand[pos] = (k & 0xFFFFC000u) | (bi + 0u);
                                       atomicAdd(&hist[min(2047u, (k - KMIN) >> 15)], 1u); }
                      pos++; }
            if (p1) { unsigned k = fkey_pos(v1);
                      if (pos < CAP) { cand[pos] = (k & 0xFFFFC000u) | (bi + 1u);
                                       atomicAdd(&hist[min(2047u, (k - KMIN) >> 15)], 1u); }
                      pos++; }
            if (p2) { unsigned k = fkey_pos(v2);
                      if (pos < CAP) { cand[pos] = (k & 0xFFFFC000u) | (bi + 2u);
                                       atomicAdd(&hist[min(2047u, (k - KMIN) >> 15)], 1u); }
                      pos++; }
            if (p3) { unsigned k = fkey_pos(v3);
                      if (pos < CAP) { cand[pos] = (k & 0xFFFFC000u) | (bi + 3u);
                                       atomicAdd(&hist[min(2047u, (k - KMIN) >> 15)], 1u); }
                      pos++; }
        }
    }
    __syncthreads();
    const unsigned total = *scnt;

    bool fast = (total >= KSEL && total <= CAP);
    unsigned b1 = 0, rem1 = 0, Ecnt = 0;
    if (fast) {
        scan_sel(hist, 2048, KSEL, gsum, bc);
        b1 = bc[0]; rem1 = bc[1]; Ecnt = bc[5];
        if (Ecnt > BCAP) fast = false;        // pathological: exact fallback below
    }

    if (fast) {
        // ---- classify: bin > b1 -> winner bit; bin == b1 -> boundary ----
        for (unsigned i = tid; i < total; i += NTHREADS) {
            unsigned c = cand[i];
            unsigned bin = min(2047u, (c - KMIN) >> 15);   // idx bits don't reach bit 15
            if (bin > b1) {
                unsigned idx = c & 0x3FFFu;
                atomicOr(&bmask[idx >> 5], 1u << (idx & 31u));
            } else if (bin == b1) {
                unsigned p = atomicAdd(bcnt, 1u);
                bidx[p] = c & 0x3FFFu;                      // p < Ecnt <= BCAP
            }
        }
        __syncthreads();

        // ---- boundary: recompute exact keys, rank (key desc, index asc) ----
        if (tid < (int)Ecnt) {
            unsigned idx = bidx[tid];
            bkey[tid] = fkey(__ldg(&xrow[idx]) * __ldg(&g_boost[idx]));
        }
        __syncthreads();
        if (tid < (int)Ecnt) {
            unsigned mk = bkey[tid], mi = bidx[tid];
            unsigned rank = 0;
            for (unsigned j = 0; j < Ecnt; j++) {
                unsigned ok = bkey[j];
                rank += (ok > mk) || (ok == mk && bidx[j] < mi);
            }
            if (rank < rem1) atomicOr(&bmask[mi >> 5], 1u << (mi & 31u));
        }
        __syncthreads();

        // ---- single output pass from bitmask ----
        #pragma unroll
        for (int it = 0; it < NIT; it++) {
            int i4 = it * NTHREADS + tid;
            unsigned w = bmask[i4 >> 3];
            unsigned f = (w >> ((i4 & 7) * 4)) & 0xFu;
            float4 o;
            o.x = (f & 1u) ? 1.0f : 0.0f;
            o.y = (f & 2u) ? 1.0f : 0.0f;
            o.z = (f & 4u) ? 1.0f : 0.0f;
            o.w = (f & 8u) ? 1.0f : 0.0f;
            __stcs(&out4[i4], o);
        }
    } else {
        // ================= FALLBACK: exact full 3-pass radix, recompute keys =================
        reinterpret_cast<uint4*>(hist)[tid] = make_uint4(0, 0, 0, 0);
        __syncthreads();
        #pragma unroll
        for (int it = 0; it < NIT; it++) {
            uint4 k = keys4_at(xin, bfv, it * NTHREADS + tid);
            atomicAdd(&hist[k.x >> 21], 1u);
            atomicAdd(&hist[k.y >> 21], 1u);
            atomicAdd(&hist[k.z >> 21], 1u);
            atomicAdd(&hist[k.w >> 21], 1u);
        }
        __syncthreads();
        scan_sel(hist, 2048, KSEL, gsum, bc);
        const unsigned fb1 = bc[0], frem1 = bc[1];
        reinterpret_cast<uint4*>(hist)[tid] = make_uint4(0, 0, 0, 0);
        __syncthreads();
        #pragma unroll
        for (int it = 0; it < NIT; it++) {
            uint4 k = keys4_at(xin, bfv, it * NTHREADS + tid);
            if ((k.x >> 21) == fb1) atomicAdd(&hist[(k.x >> 10) & 2047u], 1u);
            if ((k.y >> 21) == fb1) atomicAdd(&hist[(k.y >> 10) & 2047u], 1u);
            if ((k.z >> 21) == fb1) atomicAdd(&hist[(k.z >> 10) & 2047u], 1u);
            if ((k.w >> 21) == fb1) atomicAdd(&hist[(k.w >> 10) & 2047u], 1u);
        }
        __syncthreads();
        scan_sel(hist, 2048, frem1, gsum, bc);
        const unsigned fb2 = bc[0], frem2 = bc[1];
        const unsigned pref21 = (fb1 << 11) | fb2;
        if (tid < 256) reinterpret_cast<uint4*>(hist)[tid] = make_uint4(0, 0, 0, 0);
        __syncthreads();
        #pragma unroll
        for (int it = 0; it < NIT; it++) {
            uint4 k = keys4_at(xin, bfv, it * NTHREADS + tid);
            if ((k.x >> 10) == pref21) atomicAdd(&hist[k.x & 1023u], 1u);
            if ((k.y >> 10) == pref21) atomicAdd(&hist[k.y & 1023u], 1u);
            if ((k.z >> 10) == pref21) atomicAdd(&hist[k.z & 1023u], 1u);
            if ((k.w >> 10) == pref21) atomicAdd(&hist[k.w & 1023u], 1u);
        }
        __syncthreads();
        scan_sel(hist, 1024, frem2, gsum, bc);
        const unsigned T    = (pref21 << 10) | bc[0];
        const unsigned rem3 = bc[1];
        const unsigned EcntF = bc[5];

        if (rem3 != EcntF) {
            if (tid == 0) *scnt = 0;
            __syncthreads();
            #pragma unroll
            for (int it = 0; it < NIT; it++) {
                int i4 = it * NTHREADS + tid;
                uint4 k = keys4_at(xin, bfv, i4);
                unsigned bi = (unsigned)i4 * 4u;
                if (k.x == T) { unsigned p = atomicAdd(scnt, 1u); if (p < CAP) cand[p] = bi + 0u; }
                if (k.y == T) { unsigned p = atomicAdd(scnt, 1u); if (p < CAP) cand[p] = bi + 1u; }
                if (k.z == T) { unsigned p = atomicAdd(scnt, 1u); if (p < CAP) cand[p] = bi + 2u; }
                if (k.w == T) { unsigned p = atomicAdd(scnt, 1u); if (p < CAP) cand[p] = bi + 3u; }
            }
            __syncthreads();
            if (tid == 0) {
                unsigned cnt = *scnt; if (cnt > CAP) cnt = CAP;
                unsigned Ith = 0;
                for (unsigned r = 0; r < rem3; r++) {
                    unsigned best = 0xFFFFFFFFu, bj = 0;
                    for (unsigned j = 0; j < cnt; j++)
                        if (cand[j] < best) { best = cand[j]; bj = j; }
                    cand[bj] = 0xFFFFFFFFu;
                    Ith = best;
                }
                bc[3] = Ith;
            }
        } else if (tid == 0) {
            bc[3] = 0xFFFFFFFFu;
        }
        __syncthreads();
        const unsigned Ithr = bc[3];

        #pragma unroll
        for (int it = 0; it < NIT; it++) {
            int i4 = it * NTHREADS + tid;
            uint4 k = keys4_at(xin, bfv, i4);
            unsigned bi = (unsigned)i4 * 4u;
            float4 o;
            o.x = (k.x > T || (k.x == T && bi + 0u <= Ithr)) ? 1.0f : 0.0f;
            o.y = (k.y > T || (k.y == T && bi + 1u <= Ithr)) ? 1.0f : 0.0f;
            o.z = (k.z > T || (k.z == T && bi + 2u <= Ithr)) ? 1.0f : 0.0f;
            o.w = (k.w > T || (k.w == T && bi + 3u <= Ithr)) ? 1.0f : 0.0f;
            out4[i4] = o;
        }
    }
}

extern "C" void kernel_launch(void* const* d_in, const int* in_sizes, int n_in,
                              void* d_out, int out_size) {
    const float* x    = (const float*)d_in[0];
    const float* duty = (const float*)d_in[1];
    float* out        = (float*)d_out;
    int rows = in_sizes[0] / NCOLS;

    cudaFuncSetAttribute(kwinners_kernel,
                         cudaFuncAttributeMaxDynamicSharedMemorySize, SMEM_BYTES);

    boost_kernel<<<(NCOLS + 255) / 256, 256>>>(duty);
    kwinners_kernel<<<rows, NTHREADS, SMEM_BYTES>>>(x, out);
}